// round 10
// baseline (speedup 1.0000x reference)
#include <cuda_runtime.h>
#include <cuda_bf16.h>

#define HID 512
#define BT  16
#define TT  2048
#define ISZ 32
#define NBLK 128
#define NTH  512
#define YSZ (BT*TT*ISZ)

// ---- shared memory word (u32) layout ---------------------------------------
#define OA0   0                 // L0 A: hi 16x256 | lo 16x256 (w_hh0), swizzled
#define OA1   8192              // L1 A: hi 16x512 | lo 16x512 (w_ih1|w_hh1)
#define OB    24576             // B: hi [L(2)][b(16)][256] | lo same (raw copy of g_hp)
#define ORED  40960             // 16 warps x 256 floats
#define OBIAS 45056             // 32 floats
#define SMEM_MAIN ((OBIAS + 32) * 4)

#define PWO 516
#define SMEM_Y ((32*PWO + 16*512)*4)

// ---- device scratch ---------------------------------------------------------
__device__ __align__(16) unsigned g_hp[2][16384];   // packed split-bf16 h (64KB/buf)
__device__ float g_gx0[(size_t)TT*NBLK*256];        // precomputed x@w_ih0^T
__device__ float g_h2[(size_t)TT*BT*HID];           // layer-1 outputs
__device__ unsigned g_bar_count, g_bar_gen;

// ---- helpers ----------------------------------------------------------------
__device__ __forceinline__ void split2(float f0, float f1, unsigned &hi, unsigned &lo) {
    unsigned h;
    asm("cvt.rn.bf16x2.f32 %0, %1, %2;" : "=r"(h) : "f"(f1), "f"(f0));
    float r0 = f0 - __uint_as_float(h << 16);
    float r1 = f1 - __uint_as_float(h & 0xFFFF0000u);
    unsigned l;
    asm("cvt.rn.bf16x2.f32 %0, %1, %2;" : "=r"(l) : "f"(r1), "f"(r0));
    hi = h; lo = l;
}

__device__ __forceinline__ void mma_bf16(float* c, const unsigned* a, const unsigned* b) {
    asm volatile(
        "mma.sync.aligned.m16n8k16.row.col.f32.bf16.bf16.f32 "
        "{%0,%1,%2,%3}, {%4,%5,%6,%7}, {%8,%9}, {%0,%1,%2,%3};"
        : "+f"(c[0]), "+f"(c[1]), "+f"(c[2]), "+f"(c[3])
        : "r"(a[0]), "r"(a[1]), "r"(a[2]), "r"(a[3]), "r"(b[0]), "r"(b[1]));
}

__device__ __forceinline__ void ldsm4(unsigned &r0, unsigned &r1, unsigned &r2, unsigned &r3,
                                      unsigned addr) {
    asm volatile("ldmatrix.sync.aligned.m8n8.x4.shared.b16 {%0,%1,%2,%3}, [%4];"
                 : "=r"(r0), "=r"(r1), "=r"(r2), "=r"(r3) : "r"(addr));
}

__device__ __forceinline__ float sigf(float v) {
    return __fdividef(1.0f, 1.0f + __expf(-v));
}
__device__ __forceinline__ float tanh_fast(float v) {
    return __fdividef(2.0f, 1.0f + __expf(-2.0f * v)) - 1.0f;
}

// THE 4x-PROVEN grid barrier (R2/R3/R4/R8): atomic ticket + volatile release.
__device__ __forceinline__ void grid_barrier() {
    __syncthreads();
    if (threadIdx.x == 0) {
        volatile unsigned* genp = &g_bar_gen;
        unsigned gen = *genp;
        __threadfence();
        unsigned ticket = atomicAdd(&g_bar_count, 1u);
        if (ticket == NBLK - 1) {
            g_bar_count = 0u;   // reset before release
            __threadfence();
            atomicAdd(&g_bar_gen, 1u);
        } else {
            while (*genp == gen) { }
        }
    }
    __syncthreads();
}

// ---- init -------------------------------------------------------------------
__global__ void init_zero_kernel() {
    int i = blockIdx.x * blockDim.x + threadIdx.x;
    if (i < 2 * 16384) (&g_hp[0][0])[i] = 0u;
    if (i == 0) { g_bar_count = 0u; g_bar_gen = 0u; }
}

// gx0[t][blk][g*4+u][b] = dot(x[b,t,:], w_ih0[g*512+blk*4+u, :])
__global__ void gx0_kernel(const float* __restrict__ x, const float* __restrict__ w_ih0) {
    __shared__ float sx[BT][ISZ];
    const int t = blockIdx.x;
    const int tid = threadIdx.x;
    for (int i = tid; i < BT * ISZ; i += 256) {
        int b = i >> 5, k = i & 31;
        sx[b][k] = x[((size_t)b * TT + t) * ISZ + k];
    }
    __syncthreads();
    const int grow = blockIdx.y * 256 + tid;   // 0..2047
    float4 w[8];
    #pragma unroll
    for (int i = 0; i < 8; i++)
        w[i] = *(const float4*)&w_ih0[grow * ISZ + i * 4];
    const int g = grow >> 9, ug = grow & 511;
    const int blk = ug >> 2, u = ug & 3;
    float* outp = &g_gx0[((size_t)t * NBLK + blk) * 256 + (g * 4 + u) * 16];
    #pragma unroll 4
    for (int b = 0; b < BT; b++) {
        float s = 0.0f;
        #pragma unroll
        for (int i = 0; i < 8; i++) {
            s += w[i].x * sx[b][i*4+0] + w[i].y * sx[b][i*4+1]
               + w[i].z * sx[b][i*4+2] + w[i].w * sx[b][i*4+3];
        }
        outp[b] = s;
    }
}

// ---- main persistent kernel (plain launch, no clusters) ---------------------
__global__ void __launch_bounds__(NTH, 1) lstm_kernel(
    const float* __restrict__ w_hh0,
    const float* __restrict__ b_ih0, const float* __restrict__ b_hh0,
    const float* __restrict__ w_ih1, const float* __restrict__ w_hh1,
    const float* __restrict__ b_ih1, const float* __restrict__ b_hh1,
    float* __restrict__ out)
{
    extern __shared__ unsigned smu[];
    float* red  = reinterpret_cast<float*>(&smu[ORED]);
    float* bias = reinterpret_cast<float*>(&smu[OBIAS]);
    const int tid = threadIdx.x;
    const int bid = blockIdx.x;
    const int j0  = bid * 4;
    const unsigned sbase = (unsigned)__cvta_generic_to_shared(smu);

    // ---- one-time: split-bf16 weights into smem, XOR-swizzled ----
    for (int i = tid; i < 16 * 256; i += NTH) {
        int r = i >> 8, w = i & 255;
        int grow = (r >> 2) * HID + j0 + (r & 3);
        float f0 = w_hh0[grow * HID + 2 * w];
        float f1 = w_hh0[grow * HID + 2 * w + 1];
        unsigned hi, lo; split2(f0, f1, hi, lo);
        int ws = w ^ ((r & 7) << 2);
        smu[OA0 + r * 256 + ws]        = hi;
        smu[OA0 + 4096 + r * 256 + ws] = lo;
    }
    for (int i = tid; i < 16 * 512; i += NTH) {
        int r = i >> 9, w = i & 511;
        int grow = (r >> 2) * HID + j0 + (r & 3);
        int c0 = 2 * w, c1 = c0 + 1;
        float f0 = (c0 < 512) ? w_ih1[grow*HID + c0] : w_hh1[grow*HID + (c0 - 512)];
        float f1 = (c1 < 512) ? w_ih1[grow*HID + c1] : w_hh1[grow*HID + (c1 - 512)];
        unsigned hi, lo; split2(f0, f1, hi, lo);
        int ws = w ^ ((r & 7) << 2);
        smu[OA1 + r * 512 + ws]        = hi;
        smu[OA1 + 8192 + r * 512 + ws] = lo;
    }
    if (tid < 32) {
        int l = tid >> 4, r = tid & 15;
        int grow = (r >> 2) * HID + j0 + (r & 3);
        bias[tid] = l ? (b_ih1[grow] + b_hh1[grow]) : (b_ih0[grow] + b_hh0[grow]);
    }
    __syncthreads();

    // ---- roles ----
    const int wid = tid >> 5, lane = tid & 31;
    const int mm = lane >> 3, rr = lane & 7;
    const int ar = rr + ((mm & 1) << 3);          // A ldmatrix row
    const unsigned aoff = (unsigned)((mm >> 1) << 2);
    const int bb = ((mm >> 1) << 3) + rr;         // B ldmatrix row (batch)
    const unsigned boff = (unsigned)((mm & 1) << 2);
    const unsigned xm = (unsigned)(rr << 2);      // swizzle xor
    const int layerA = tid >> 6, uA = (tid >> 4) & 3, bA = tid & 15;
    float c_reg = 0.0f, h_last = 0.0f;

    // SMSP-balanced k-tile split:
    //  L0 warps 0-5: counts {5,5,6,6,5,5}, starts 5w+clamp(w-2,0,2)  (32 tiles)
    //  L1 warps 6-15 (j=wid-6): counts 6+((j>>1)&1), starts 6j+2*(j>>2)+((j&3)==3)
    int ktile_start, ktile_cnt;
    if (wid < 6) {
        int cw = wid - 2; cw = cw < 0 ? 0 : (cw > 2 ? 2 : cw);
        ktile_start = 5 * wid + cw;
        ktile_cnt   = 5 + ((wid == 2) | (wid == 3));
    } else {
        int j = wid - 6;
        ktile_start = 6 * j + 2 * (j >> 2) + ((j & 3) == 3 ? 1 : 0);
        ktile_cnt   = 6 + ((j >> 1) & 1);
    }

    for (int n = 0; n <= TT; n++) {
        const int wr = n & 1, rd = wr ^ 1;

        // ---- prefetch gx0 (L0 act threads) ----
        float gx[4] = {0, 0, 0, 0};
        if (tid < 64 && n < TT) {
            const float* gp = &g_gx0[((size_t)n * NBLK + bid) * 256 + uA * 16 + bA];
            #pragma unroll
            for (int g = 0; g < 4; g++) gx[g] = __ldg(gp + g * 64);
        }

        // ---- deferred g_h2 store (off the pre-barrier critical path) ----
        if (n >= 2 && tid >= 64 && tid < 128)
            g_h2[((size_t)(n - 2) * BT + bA) * HID + j0 + uA] = h_last;

        // ---- stage packed h (raw linear copy; layout already swizzled) ----
        {
            const uint4* src = (const uint4*)&g_hp[rd][0];
            #pragma unroll
            for (int it = 0; it < 8; it++) {
                int i = tid + it * NTH;            // 0..4095
                *(uint4*)&smu[OB + i * 4] = __ldcg(&src[i]);
            }
        }
        __syncthreads();

        // ---- tensor-core GEMMs (split-bf16, A+B via ldmatrix) ----
        if (wid < 6) {
            if (n < TT) {   // layer 0: K=512, tiles [ktile_start, +cnt)
                float acc0[4] = {0,0,0,0}, acc1[4] = {0,0,0,0};
                for (int i = 0; i < ktile_cnt; i++) {
                    const unsigned w = (unsigned)((ktile_start + i) * 8);
                    unsigned aw = sbase + (OA0 + ar * 256 + ((w + aoff) ^ xm)) * 4u;
                    unsigned bw = sbase + (OB  + bb * 256 + ((w + boff) ^ xm)) * 4u;
                    unsigned ah[4], al[4], b0,b1,b2,b3, l0,l1,l2,l3;
                    ldsm4(ah[0], ah[1], ah[2], ah[3], aw);
                    ldsm4(al[0], al[1], al[2], al[3], aw + 4096 * 4u);
                    ldsm4(b0, b1, b2, b3, bw);
                    ldsm4(l0, l1, l2, l3, bw + 8192 * 4u);
                    unsigned bh0[2] = {b0, b1}, bh1[2] = {b2, b3};
                    unsigned bl0[2] = {l0, l1}, bl1[2] = {l2, l3};
                    mma_bf16(acc0, ah, bh0);
                    mma_bf16(acc0, ah, bl0);
                    mma_bf16(acc0, al, bh0);
                    mma_bf16(acc1, ah, bh1);
                    mma_bf16(acc1, ah, bl1);
                    mma_bf16(acc1, al, bh1);
                }
                const int base = wid * 256, row = lane >> 2, col = (lane & 3) * 2;
                *(float2*)&red[base +  row      * 16 + col    ] = make_float2(acc0[0], acc0[1]);
                *(float2*)&red[base + (row + 8) * 16 + col    ] = make_float2(acc0[2], acc0[3]);
                *(float2*)&red[base +  row      * 16 + col + 8] = make_float2(acc1[0], acc1[1]);
                *(float2*)&red[base + (row + 8) * 16 + col + 8] = make_float2(acc1[2], acc1[3]);
            }
        } else {
            if (n >= 1) {   // layer 1: K=1024, tiles [ktile_start, +cnt) of 64
                float acc0[4] = {0,0,0,0}, acc1[4] = {0,0,0,0};
                for (int i = 0; i < ktile_cnt; i++) {
                    const int kt = ktile_start + i;
                    const unsigned wA = (unsigned)(kt * 8);
                    const unsigned Lb = (kt >= 32) ? 4096u : 0u;
                    const unsigned wB = (unsigned)(((kt >= 32) ? kt - 32 : kt) * 8);
                    unsigned aw = sbase + (OA1 + ar * 512 + ((wA + aoff) ^ xm)) * 4u;
                    unsigned bw = sbase + (OB + Lb + bb * 256 + ((wB + boff) ^ xm)) * 4u;
                    unsigned ah[4], al[4], b0,b1,b2,b3, l0,l1,l2,l3;
                    ldsm4(ah[0], ah[1], ah[2], ah[3], aw);
                    ldsm4(al[0], al[1], al[2], al[3], aw + 8192 * 4u);
                    ldsm4(b0, b1, b2, b3, bw);
                    ldsm4(l0, l1, l2, l3, bw + 8192 * 4u);
                    unsigned bh0[2] = {b0, b1}, bh1[2] = {b2, b3};
                    unsigned bl0[2] = {l0, l1}, bl1[2] = {l2, l3};
                    mma_bf16(acc0, ah, bh0);
                    mma_bf16(acc0, ah, bl0);
                    mma_bf16(acc0, al, bh0);
                    mma_bf16(acc1, ah, bh1);
                    mma_bf16(acc1, ah, bl1);
                    mma_bf16(acc1, al, bh1);
                }
                const int base = wid * 256, row = lane >> 2, col = (lane & 3) * 2;
                *(float2*)&red[base +  row      * 16 + col    ] = make_float2(acc0[0], acc0[1]);
                *(float2*)&red[base + (row + 8) * 16 + col    ] = make_float2(acc0[2], acc0[3]);
                *(float2*)&red[base +  row      * 16 + col + 8] = make_float2(acc1[0], acc1[1]);
                *(float2*)&red[base + (row + 8) * 16 + col + 8] = make_float2(acc1[2], acc1[3]);
            }
        }
        __syncthreads();

        // ---- merged reduce + activations + state update + publish ----
        if (tid < 128) {
            const bool active = layerA ? (n >= 1) : (n < TT);
            if (active) {
                float g4[4];
                #pragma unroll
                for (int g = 0; g < 4; g++) {
                    const int row = g * 4 + uA;
                    const int idx = row * 16 + bA;
                    float s;
                    if (layerA == 0) {          // slabs 0..5
                        const float* rp = &red[idx];
                        s = rp[0] + rp[256] + rp[512] + rp[768] + rp[1024] + rp[1280];
                    } else {                    // slabs 6..15
                        const float* rp = &red[6 * 256 + idx];
                        s = rp[0] + rp[256] + rp[512] + rp[768] + rp[1024]
                          + rp[1280] + rp[1536] + rp[1792] + rp[2048] + rp[2304];
                    }
                    g4[g] = s + bias[layerA * 16 + row] + gx[g];
                }
                float iv = sigf(g4[0]), fv = sigf(g4[1]);
                float gg = tanh_fast(g4[2]), ov = sigf(g4[3]);
                c_reg = fv * c_reg + iv * gg;
                h_last = ov * tanh_fast(c_reg);

                float hp = __shfl_xor_sync(0xffffffffu, h_last, 16);
                if ((tid & 16) == 0) {
                    unsigned whi, wlo; split2(h_last, hp, whi, wlo);
                    const int w  = bid * 2 + (uA >> 1);
                    const int ws = w ^ ((bA & 7) << 2);
                    g_hp[wr][layerA * 4096 + bA * 256 + ws]        = whi;
                    g_hp[wr][8192 + layerA * 4096 + bA * 256 + ws] = wlo;
                }
            }
        }
        __threadfence();
        grid_barrier();
    }

    // ---- epilogue: last g_h2 step + final h_n, c_n ----
    if (tid >= 64 && tid < 128)
        g_h2[((size_t)(TT - 1) * BT + bA) * HID + j0 + uA] = h_last;
    if (tid < 128) {
        const int j = j0 + uA;
        out[YSZ + (layerA * BT + bA) * HID + j] = h_last;
        out[YSZ + 2*BT*HID + (layerA * BT + bA) * HID + j] = c_reg;
    }
}

// ---- y projection -----------------------------------------------------------
__global__ void __launch_bounds__(256) y_proj_kernel(
    const float* __restrict__ w_out, const float* __restrict__ b_out,
    float* __restrict__ out)
{
    extern __shared__ float sm[];
    float* sWo = sm;
    float* sH  = sm + 32 * PWO;
    const int t = blockIdx.x;
    const int tid = threadIdx.x;

    for (int i = tid; i < 32 * 128; i += 256) {
        int o = i >> 7, k = (i & 127) << 2;
        *(float4*)&sWo[o * PWO + k] = *(const float4*)&w_out[o * HID + k];
    }
    for (int i = tid; i < 16 * 128; i += 256) {
        int b = i >> 7, k = (i & 127) << 2;
        *(float4*)&sH[b * HID + k] = *(const float4*)&g_h2[((size_t)t * BT + b) * HID + k];
    }
    __syncthreads();

    const int b = tid >> 4, oc = tid & 15;
    float a0 = 0.0f, a1 = 0.0f;
    #pragma unroll 4
    for (int k = 0; k < HID; k += 4) {
        float4 hk = *(const float4*)&sH[b * HID + k];
        float4 w0 = *(const float4*)&sWo[oc * PWO + k];
        float4 w1 = *(const float4*)&sWo[(oc + 16) * PWO + k];
        a0 += hk.x*w0.x + hk.y*w0.y + hk.z*w0.z + hk.w*w0.w;
        a1 += hk.x*w1.x + hk.y*w1.y + hk.z*w1.z + hk.w*w1.w;
    }
    out[((size_t)b * TT + t) * ISZ + oc]      = a0 + b_out[oc];
    out[((size_t)b * TT + t) * ISZ + oc + 16] = a1 + b_out[oc + 16];
}

// ----------------------------------------------------------------------------
extern "C" void kernel_launch(void* const* d_in, const int* in_sizes, int n_in,
                              void* d_out, int out_size)
{
    const float* x     = (const float*)d_in[0];
    const float* w_ih0 = (const float*)d_in[1];
    const float* w_hh0 = (const float*)d_in[2];
    const float* b_ih0 = (const float*)d_in[3];
    const float* b_hh0 = (const float*)d_in[4];
    const float* w_ih1 = (const float*)d_in[5];
    const float* w_hh1 = (const float*)d_in[6];
    const float* b_ih1 = (const float*)d_in[7];
    const float* b_hh1 = (const float*)d_in[8];
    const float* w_out = (const float*)d_in[9];
    const float* b_out = (const float*)d_in[10];
    float* out = (float*)d_out;

    cudaFuncSetAttribute(lstm_kernel, cudaFuncAttributeMaxDynamicSharedMemorySize, SMEM_MAIN);
    cudaFuncSetAttribute(y_proj_kernel, cudaFuncAttributeMaxDynamicSharedMemorySize, SMEM_Y);

    init_zero_kernel<<<128, 256>>>();
    {
        dim3 g(TT, 8, 1);
        gx0_kernel<<<g, 256>>>(x, w_ih0);
    }
    lstm_kernel<<<NBLK, NTH, SMEM_MAIN>>>(w_hh0, b_ih0, b_hh0,
                                          w_ih1, w_hh1, b_ih1, b_hh1, out);
    y_proj_kernel<<<TT, 256, SMEM_Y>>>(w_out, b_out, out);
}

// round 11
// speedup vs baseline: 1.0282x; 1.0282x over previous
#include <cuda_runtime.h>
#include <cuda_bf16.h>

#define HID 512
#define BT  16
#define TT  2048
#define ISZ 32
#define NBLK 128
#define NTH  512
#define YSZ (BT*TT*ISZ)

// ---- shared memory word (u32) layout ---------------------------------------
#define OA0   0                 // L0 A: hi 16x256 | lo 16x256 (w_hh0), swizzled
#define OA1   8192              // L1 A: hi 16x512 | lo 16x512 (w_ih1|w_hh1)
#define OB    24576             // B: hi [L(2)][b(16)][256] | lo same (TMA copy of g_hp)
#define ORED  40960             // 16 warps x 256 floats
#define OBIAS 45056             // 32 floats
#define OMBAR 45088             // u64 mbarrier (8-byte aligned: 45088*4 % 8 == 0)
#define SMEM_MAIN ((OMBAR + 2) * 4)

#define PWO 516
#define SMEM_Y ((32*PWO + 16*512)*4)

// ---- device scratch ---------------------------------------------------------
__device__ __align__(16) unsigned g_hp[2][16384];   // packed split-bf16 h (64KB/buf)
__device__ float g_gx0[(size_t)TT*NBLK*256];        // precomputed x@w_ih0^T
__device__ float g_h2[(size_t)TT*BT*HID];           // layer-1 outputs
__device__ unsigned g_bar_count, g_bar_gen;

// ---- helpers ----------------------------------------------------------------
__device__ __forceinline__ void split2(float f0, float f1, unsigned &hi, unsigned &lo) {
    unsigned h;
    asm("cvt.rn.bf16x2.f32 %0, %1, %2;" : "=r"(h) : "f"(f1), "f"(f0));
    float r0 = f0 - __uint_as_float(h << 16);
    float r1 = f1 - __uint_as_float(h & 0xFFFF0000u);
    unsigned l;
    asm("cvt.rn.bf16x2.f32 %0, %1, %2;" : "=r"(l) : "f"(r1), "f"(r0));
    hi = h; lo = l;
}

__device__ __forceinline__ void mma_bf16(float* c, const unsigned* a, const unsigned* b) {
    asm volatile(
        "mma.sync.aligned.m16n8k16.row.col.f32.bf16.bf16.f32 "
        "{%0,%1,%2,%3}, {%4,%5,%6,%7}, {%8,%9}, {%0,%1,%2,%3};"
        : "+f"(c[0]), "+f"(c[1]), "+f"(c[2]), "+f"(c[3])
        : "r"(a[0]), "r"(a[1]), "r"(a[2]), "r"(a[3]), "r"(b[0]), "r"(b[1]));
}

__device__ __forceinline__ void ldsm4(unsigned &r0, unsigned &r1, unsigned &r2, unsigned &r3,
                                      unsigned addr) {
    asm volatile("ldmatrix.sync.aligned.m8n8.x4.shared.b16 {%0,%1,%2,%3}, [%4];"
                 : "=r"(r0), "=r"(r1), "=r"(r2), "=r"(r3) : "r"(addr));
}

__device__ __forceinline__ float sigf(float v) {
    return __fdividef(1.0f, 1.0f + __expf(-v));
}
__device__ __forceinline__ float tanh_fast(float v) {
    return __fdividef(2.0f, 1.0f + __expf(-2.0f * v)) - 1.0f;
}

// CTA-local mbarrier ops (no clusters anywhere)
__device__ __forceinline__ void mbar_init(unsigned mbar, unsigned cnt) {
    asm volatile("mbarrier.init.shared.b64 [%0], %1;" :: "r"(mbar), "r"(cnt) : "memory");
}
__device__ __forceinline__ void mbar_expect(unsigned mbar, unsigned bytes) {
    asm volatile("mbarrier.arrive.expect_tx.shared.b64 _, [%0], %1;"
                 :: "r"(mbar), "r"(bytes) : "memory");
}
__device__ __forceinline__ void mbar_wait(unsigned mbar, unsigned parity) {
    asm volatile(
        "{\n\t"
        ".reg .pred P;\n\t"
        "WL%=:\n\t"
        "mbarrier.try_wait.parity.acquire.cta.shared::cta.b64 P, [%0], %1, 0x989680;\n\t"
        "@!P bra WL%=;\n\t"
        "}"
        :: "r"(mbar), "r"(parity) : "memory");
}
__device__ __forceinline__ void bulk_g2s(unsigned dst, const void* src, unsigned bytes,
                                         unsigned mbar) {
    asm volatile(
        "cp.async.bulk.shared::cluster.global.mbarrier::complete_tx::bytes "
        "[%0], [%1], %2, [%3];"
        :: "r"(dst), "l"(src), "r"(bytes), "r"(mbar) : "memory");
}

// THE 4x-PROVEN grid barrier (R2/R3/R4/R8): atomic ticket + volatile release.
__device__ __forceinline__ void grid_barrier() {
    __syncthreads();
    if (threadIdx.x == 0) {
        volatile unsigned* genp = &g_bar_gen;
        unsigned gen = *genp;
        __threadfence();
        unsigned ticket = atomicAdd(&g_bar_count, 1u);
        if (ticket == NBLK - 1) {
            g_bar_count = 0u;   // reset before release
            __threadfence();
            atomicAdd(&g_bar_gen, 1u);
        } else {
            while (*genp == gen) { }
        }
    }
    __syncthreads();
}

// ---- init -------------------------------------------------------------------
__global__ void init_zero_kernel() {
    int i = blockIdx.x * blockDim.x + threadIdx.x;
    if (i < 2 * 16384) (&g_hp[0][0])[i] = 0u;
    if (i == 0) { g_bar_count = 0u; g_bar_gen = 0u; }
}

// gx0[t][blk][g*4+u][b] = dot(x[b,t,:], w_ih0[g*512+blk*4+u, :])
__global__ void gx0_kernel(const float* __restrict__ x, const float* __restrict__ w_ih0) {
    __shared__ float sx[BT][ISZ];
    const int t = blockIdx.x;
    const int tid = threadIdx.x;
    for (int i = tid; i < BT * ISZ; i += 256) {
        int b = i >> 5, k = i & 31;
        sx[b][k] = x[((size_t)b * TT + t) * ISZ + k];
    }
    __syncthreads();
    const int grow = blockIdx.y * 256 + tid;   // 0..2047
    float4 w[8];
    #pragma unroll
    for (int i = 0; i < 8; i++)
        w[i] = *(const float4*)&w_ih0[grow * ISZ + i * 4];
    const int g = grow >> 9, ug = grow & 511;
    const int blk = ug >> 2, u = ug & 3;
    float* outp = &g_gx0[((size_t)t * NBLK + blk) * 256 + (g * 4 + u) * 16];
    #pragma unroll 4
    for (int b = 0; b < BT; b++) {
        float s = 0.0f;
        #pragma unroll
        for (int i = 0; i < 8; i++) {
            s += w[i].x * sx[b][i*4+0] + w[i].y * sx[b][i*4+1]
               + w[i].z * sx[b][i*4+2] + w[i].w * sx[b][i*4+3];
        }
        outp[b] = s;
    }
}

// ---- main persistent kernel (plain launch, no clusters) ---------------------
__global__ void __launch_bounds__(NTH, 1) lstm_kernel(
    const float* __restrict__ w_hh0,
    const float* __restrict__ b_ih0, const float* __restrict__ b_hh0,
    const float* __restrict__ w_ih1, const float* __restrict__ w_hh1,
    const float* __restrict__ b_ih1, const float* __restrict__ b_hh1,
    float* __restrict__ out)
{
    extern __shared__ unsigned smu[];
    float* red  = reinterpret_cast<float*>(&smu[ORED]);
    float* bias = reinterpret_cast<float*>(&smu[OBIAS]);
    const int tid = threadIdx.x;
    const int bid = blockIdx.x;
    const int j0  = bid * 4;
    const unsigned sbase = (unsigned)__cvta_generic_to_shared(smu);
    const unsigned mbar  = sbase + OMBAR * 4u;

    // ---- one-time: split-bf16 weights into smem, XOR-swizzled ----
    for (int i = tid; i < 16 * 256; i += NTH) {
        int r = i >> 8, w = i & 255;
        int grow = (r >> 2) * HID + j0 + (r & 3);
        float f0 = w_hh0[grow * HID + 2 * w];
        float f1 = w_hh0[grow * HID + 2 * w + 1];
        unsigned hi, lo; split2(f0, f1, hi, lo);
        int ws = w ^ ((r & 7) << 2);
        smu[OA0 + r * 256 + ws]        = hi;
        smu[OA0 + 4096 + r * 256 + ws] = lo;
    }
    for (int i = tid; i < 16 * 512; i += NTH) {
        int r = i >> 9, w = i & 511;
        int grow = (r >> 2) * HID + j0 + (r & 3);
        int c0 = 2 * w, c1 = c0 + 1;
        float f0 = (c0 < 512) ? w_ih1[grow*HID + c0] : w_hh1[grow*HID + (c0 - 512)];
        float f1 = (c1 < 512) ? w_ih1[grow*HID + c1] : w_hh1[grow*HID + (c1 - 512)];
        unsigned hi, lo; split2(f0, f1, hi, lo);
        int ws = w ^ ((r & 7) << 2);
        smu[OA1 + r * 512 + ws]        = hi;
        smu[OA1 + 8192 + r * 512 + ws] = lo;
    }
    if (tid < 32) {
        int l = tid >> 4, r = tid & 15;
        int grow = (r >> 2) * HID + j0 + (r & 3);
        bias[tid] = l ? (b_ih1[grow] + b_hh1[grow]) : (b_ih0[grow] + b_hh0[grow]);
    }
    if (tid == 0) mbar_init(mbar, 1);
    __syncthreads();

    // ---- roles ----
    const int wid = tid >> 5, lane = tid & 31;
    const int mm = lane >> 3, rr = lane & 7;
    const int ar = rr + ((mm & 1) << 3);          // A ldmatrix row
    const unsigned aoff = (unsigned)((mm >> 1) << 2);
    const int bb = ((mm >> 1) << 3) + rr;         // B ldmatrix row (batch)
    const unsigned boff = (unsigned)((mm & 1) << 2);
    const unsigned xm = (unsigned)(rr << 2);      // swizzle xor
    const int layerA = tid >> 6, uA = (tid >> 4) & 3, bA = tid & 15;
    float c_reg = 0.0f, h_last = 0.0f;

    for (int n = 0; n <= TT; n++) {
        const int wr = n & 1, rd = wr ^ 1;

        // ---- stage packed h via one TMA bulk copy (engine does the work) ----
        if (tid == 0) {
            mbar_expect(mbar, 65536u);
            bulk_g2s(sbase + OB * 4u, (const void*)&g_hp[rd][0], 65536u, mbar);
        }

        // ---- prefetch gx0 (L0 act threads) — overlaps TMA in flight ----
        float gx[4] = {0, 0, 0, 0};
        if (tid < 64 && n < TT) {
            const float* gp = &g_gx0[((size_t)n * NBLK + bid) * 256 + uA * 16 + bA];
            #pragma unroll
            for (int g = 0; g < 4; g++) gx[g] = __ldg(gp + g * 64);
        }

        // ---- wait for B data ----
        mbar_wait(mbar, (unsigned)(n & 1));

        // ---- tensor-core GEMMs (split-bf16, A+B via ldmatrix) ----
        if (wid < 8) {
            if (n < TT) {   // layer 0: K=512, K-split 8, 4 k-tiles each
                float acc0[4] = {0,0,0,0}, acc1[4] = {0,0,0,0};
                const unsigned w0 = (unsigned)(wid * 32);
                #pragma unroll
                for (int i = 0; i < 4; i++) {
                    const unsigned w = w0 + i * 8;
                    unsigned aw = sbase + (OA0 + ar * 256 + ((w + aoff) ^ xm)) * 4u;
                    unsigned bw = sbase + (OB  + bb * 256 + ((w + boff) ^ xm)) * 4u;
                    unsigned ah[4], al[4], b0,b1,b2,b3, l0,l1,l2,l3;
                    ldsm4(ah[0], ah[1], ah[2], ah[3], aw);
                    ldsm4(al[0], al[1], al[2], al[3], aw + 4096 * 4u);
                    ldsm4(b0, b1, b2, b3, bw);
                    ldsm4(l0, l1, l2, l3, bw + 8192 * 4u);
                    unsigned bh0[2] = {b0, b1}, bh1[2] = {b2, b3};
                    unsigned bl0[2] = {l0, l1}, bl1[2] = {l2, l3};
                    mma_bf16(acc0, ah, bh0);
                    mma_bf16(acc0, ah, bl0);
                    mma_bf16(acc0, al, bh0);
                    mma_bf16(acc1, ah, bh1);
                    mma_bf16(acc1, ah, bl1);
                    mma_bf16(acc1, al, bh1);
                }
                const int base = wid * 256, row = lane >> 2, col = (lane & 3) * 2;
                *(float2*)&red[base +  row      * 16 + col    ] = make_float2(acc0[0], acc0[1]);
                *(float2*)&red[base + (row + 8) * 16 + col    ] = make_float2(acc0[2], acc0[3]);
                *(float2*)&red[base +  row      * 16 + col + 8] = make_float2(acc1[0], acc1[1]);
                *(float2*)&red[base + (row + 8) * 16 + col + 8] = make_float2(acc1[2], acc1[3]);
            }
        } else {
            if (n >= 1) {   // layer 1: K=1024, K-split 8, 8 k-tiles each
                float acc0[4] = {0,0,0,0}, acc1[4] = {0,0,0,0};
                const unsigned wA0 = (unsigned)((wid - 8) * 64);
                const unsigned Lb  = (wid >= 12) ? 4096u : 0u;
                const unsigned wB0 = (wid >= 12) ? wA0 - 256u : wA0;
                #pragma unroll
                for (int i = 0; i < 8; i++) {
                    const unsigned wA = wA0 + i * 8, wB = wB0 + i * 8;
                    unsigned aw = sbase + (OA1 + ar * 512 + ((wA + aoff) ^ xm)) * 4u;
                    unsigned bw = sbase + (OB + Lb + bb * 256 + ((wB + boff) ^ xm)) * 4u;
                    unsigned ah[4], al[4], b0,b1,b2,b3, l0,l1,l2,l3;
                    ldsm4(ah[0], ah[1], ah[2], ah[3], aw);
                    ldsm4(al[0], al[1], al[2], al[3], aw + 8192 * 4u);
                    ldsm4(b0, b1, b2, b3, bw);
                    ldsm4(l0, l1, l2, l3, bw + 8192 * 4u);
                    unsigned bh0[2] = {b0, b1}, bh1[2] = {b2, b3};
                    unsigned bl0[2] = {l0, l1}, bl1[2] = {l2, l3};
                    mma_bf16(acc0, ah, bh0);
                    mma_bf16(acc0, ah, bl0);
                    mma_bf16(acc0, al, bh0);
                    mma_bf16(acc1, ah, bh1);
                    mma_bf16(acc1, ah, bl1);
                    mma_bf16(acc1, al, bh1);
                }
                const int base = wid * 256, row = lane >> 2, col = (lane & 3) * 2;
                *(float2*)&red[base +  row      * 16 + col    ] = make_float2(acc0[0], acc0[1]);
                *(float2*)&red[base + (row + 8) * 16 + col    ] = make_float2(acc0[2], acc0[3]);
                *(float2*)&red[base +  row      * 16 + col + 8] = make_float2(acc1[0], acc1[1]);
                *(float2*)&red[base + (row + 8) * 16 + col + 8] = make_float2(acc1[2], acc1[3]);
            }
        }
        __syncthreads();

        // ---- merged reduce + activations + state update + publish ----
        if (tid < 128) {
            const bool active = layerA ? (n >= 1) : (n < TT);
            if (active) {
                float g4[4];
                const int rb = layerA * 2048;
                #pragma unroll
                for (int g = 0; g < 4; g++) {
                    const int row = g * 4 + uA;
                    const float* rp = &red[rb + row * 16 + bA];
                    float s = rp[0] + rp[256] + rp[512] + rp[768]
                            + rp[1024] + rp[1280] + rp[1536] + rp[1792];
                    g4[g] = s + bias[layerA * 16 + row] + gx[g];
                }
                float iv = sigf(g4[0]), fv = sigf(g4[1]);
                float gg = tanh_fast(g4[2]), ov = sigf(g4[3]);
                c_reg = fv * c_reg + iv * gg;
                h_last = ov * tanh_fast(c_reg);

                float hp = __shfl_xor_sync(0xffffffffu, h_last, 16);
                if ((tid & 16) == 0) {
                    unsigned whi, wlo; split2(h_last, hp, whi, wlo);
                    const int w  = bid * 2 + (uA >> 1);
                    const int ws = w ^ ((bA & 7) << 2);
                    g_hp[wr][layerA * 4096 + bA * 256 + ws]        = whi;
                    g_hp[wr][8192 + layerA * 4096 + bA * 256 + ws] = wlo;
                }
                if (layerA == 1)
                    g_h2[((size_t)(n - 1) * BT + bA) * HID + j0 + uA] = h_last;
            }
        }
        if (tid < 128) __threadfence();   // only publishers fence
        grid_barrier();
    }

    // ---- final h_n, c_n ----
    if (tid < 128) {
        const int j = j0 + uA;
        out[YSZ + (layerA * BT + bA) * HID + j] = h_last;
        out[YSZ + 2*BT*HID + (layerA * BT + bA) * HID + j] = c_reg;
    }
}

// ---- y projection -----------------------------------------------------------
__global__ void __launch_bounds__(256) y_proj_kernel(
    const float* __restrict__ w_out, const float* __restrict__ b_out,
    float* __restrict__ out)
{
    extern __shared__ float sm[];
    float* sWo = sm;
    float* sH  = sm + 32 * PWO;
    const int t = blockIdx.x;
    const int tid = threadIdx.x;

    for (int i = tid; i < 32 * 128; i += 256) {
        int o = i >> 7, k = (i & 127) << 2;
        *(float4*)&sWo[o * PWO + k] = *(const float4*)&w_out[o * HID + k];
    }
    for (int i = tid; i < 16 * 128; i += 256) {
        int b = i >> 7, k = (i & 127) << 2;
        *(float4*)&sH[b * HID + k] = *(const float4*)&g_h2[((size_t)t * BT + b) * HID + k];
    }
    __syncthreads();

    const int b = tid >> 4, oc = tid & 15;
    float a0 = 0.0f, a1 = 0.0f;
    #pragma unroll 4
    for (int k = 0; k < HID; k += 4) {
        float4 hk = *(const float4*)&sH[b * HID + k];
        float4 w0 = *(const float4*)&sWo[oc * PWO + k];
        float4 w1 = *(const float4*)&sWo[(oc + 16) * PWO + k];
        a0 += hk.x*w0.x + hk.y*w0.y + hk.z*w0.z + hk.w*w0.w;
        a1 += hk.x*w1.x + hk.y*w1.y + hk.z*w1.z + hk.w*w1.w;
    }
    out[((size_t)b * TT + t) * ISZ + oc]      = a0 + b_out[oc];
    out[((size_t)b * TT + t) * ISZ + oc + 16] = a1 + b_out[oc + 16];
}

// ----------------------------------------------------------------------------
extern "C" void kernel_launch(void* const* d_in, const int* in_sizes, int n_in,
                              void* d_out, int out_size)
{
    const float* x     = (const float*)d_in[0];
    const float* w_ih0 = (const float*)d_in[1];
    const float* w_hh0 = (const float*)d_in[2];
    const float* b_ih0 = (const float*)d_in[3];
    const float* b_hh0 = (const float*)d_in[4];
    const float* w_ih1 = (const float*)d_in[5];
    const float* w_hh1 = (const float*)d_in[6];
    const float* b_ih1 = (const float*)d_in[7];
    const float* b_hh1 = (const float*)d_in[8];
    const float* w_out = (const float*)d_in[9];
    const float* b_out = (const float*)d_in[10];
    float* out = (float*)d_out;

    cudaFuncSetAttribute(lstm_kernel, cudaFuncAttributeMaxDynamicSharedMemorySize, SMEM_MAIN);
    cudaFuncSetAttribute(y_proj_kernel, cudaFuncAttributeMaxDynamicSharedMemorySize, SMEM_Y);

    init_zero_kernel<<<128, 256>>>();
    {
        dim3 g(TT, 8, 1);
        gx0_kernel<<<g, 256>>>(x, w_ih0);
    }
    lstm_kernel<<<NBLK, NTH, SMEM_MAIN>>>(w_hh0, b_ih0, b_hh0,
                                          w_ih1, w_hh1, b_ih1, b_hh1, out);
    y_proj_kernel<<<TT, 256, SMEM_Y>>>(w_out, b_out, out);
}

// round 12
// speedup vs baseline: 1.0580x; 1.0290x over previous
#include <cuda_runtime.h>
#include <cuda_bf16.h>

#define HID 512
#define BT  16
#define TT  2048
#define ISZ 32
#define NBLK 128
#define NTH  512
#define YSZ (BT*TT*ISZ)

// ---- shared memory word (u32) layout ---------------------------------------
#define OA0   0                 // L0 A: hi 16x256 | lo 16x256 (w_hh0), swizzled
#define OA1   8192              // L1 A: hi 16x512 | lo 16x512 (w_ih1|w_hh1)
#define OB    24576             // B: hi [L(2)][b(16)][256] | lo same (raw copy of g_hp)
#define ORED  40960             // 16 warps x 256 floats
#define OBIAS 45056             // 32 floats
#define SMEM_MAIN ((OBIAS + 32) * 4)

#define PWO 516
#define SMEM_Y ((32*PWO + 16*512)*4)

// ---- device scratch ---------------------------------------------------------
__device__ __align__(16) unsigned g_hp[2][16384];   // packed split-bf16 h (64KB/buf)
__device__ float g_gx0[(size_t)TT*NBLK*256];        // precomputed x@w_ih0^T
__device__ float g_h2[(size_t)TT*BT*HID];           // layer-1 outputs
__device__ unsigned g_bar_count, g_bar_gen;

// ---- helpers ----------------------------------------------------------------
__device__ __forceinline__ void split2(float f0, float f1, unsigned &hi, unsigned &lo) {
    unsigned h;
    asm("cvt.rn.bf16x2.f32 %0, %1, %2;" : "=r"(h) : "f"(f1), "f"(f0));
    float r0 = f0 - __uint_as_float(h << 16);
    float r1 = f1 - __uint_as_float(h & 0xFFFF0000u);
    unsigned l;
    asm("cvt.rn.bf16x2.f32 %0, %1, %2;" : "=r"(l) : "f"(r1), "f"(r0));
    hi = h; lo = l;
}

__device__ __forceinline__ void mma_bf16(float* c, const unsigned* a, const unsigned* b) {
    asm volatile(
        "mma.sync.aligned.m16n8k16.row.col.f32.bf16.bf16.f32 "
        "{%0,%1,%2,%3}, {%4,%5,%6,%7}, {%8,%9}, {%0,%1,%2,%3};"
        : "+f"(c[0]), "+f"(c[1]), "+f"(c[2]), "+f"(c[3])
        : "r"(a[0]), "r"(a[1]), "r"(a[2]), "r"(a[3]), "r"(b[0]), "r"(b[1]));
}

__device__ __forceinline__ void ldsm4(unsigned &r0, unsigned &r1, unsigned &r2, unsigned &r3,
                                      unsigned addr) {
    asm volatile("ldmatrix.sync.aligned.m8n8.x4.shared.b16 {%0,%1,%2,%3}, [%4];"
                 : "=r"(r0), "=r"(r1), "=r"(r2), "=r"(r3) : "r"(addr));
}

__device__ __forceinline__ float sigf(float v) {
    return __fdividef(1.0f, 1.0f + __expf(-v));
}
__device__ __forceinline__ float tanh_fast(float v) {
    return __fdividef(2.0f, 1.0f + __expf(-2.0f * v)) - 1.0f;
}

// Evolved proven barrier: monotonic ticket count (no reset), locally computed
// target (no gen pre-read), single-writer plain-store release.
// Liveness: a block reaches iteration n's barrier only after gen >= n, so its
// ticket lies in [n*NBLK, (n+1)*NBLK); the last ticket (n+1)*NBLK-1 exists and
// exactly one block takes the release branch per iteration.
__device__ __forceinline__ void grid_barrier(unsigned target) {
    __syncthreads();
    if (threadIdx.x == 0) {
        unsigned ticket = atomicAdd(&g_bar_count, 1u);
        if (ticket == target * NBLK - 1u) {
            __threadfence();
            *(volatile unsigned*)&g_bar_gen = target;
        } else {
            volatile unsigned* genp = &g_bar_gen;
            while (*genp < target) { }
        }
        asm volatile("fence.acq_rel.gpu;" ::: "memory");  // acquire for h reads
    }
    __syncthreads();
}

// ---- init -------------------------------------------------------------------
__global__ void init_zero_kernel() {
    int i = blockIdx.x * blockDim.x + threadIdx.x;
    if (i < 2 * 16384) (&g_hp[0][0])[i] = 0u;
    if (i == 0) { g_bar_count = 0u; g_bar_gen = 0u; }
}

// gx0[t][blk][g*4+u][b] = dot(x[b,t,:], w_ih0[g*512+blk*4+u, :])
__global__ void gx0_kernel(const float* __restrict__ x, const float* __restrict__ w_ih0) {
    __shared__ float sx[BT][ISZ];
    const int t = blockIdx.x;
    const int tid = threadIdx.x;
    for (int i = tid; i < BT * ISZ; i += 256) {
        int b = i >> 5, k = i & 31;
        sx[b][k] = x[((size_t)b * TT + t) * ISZ + k];
    }
    __syncthreads();
    const int grow = blockIdx.y * 256 + tid;   // 0..2047
    float4 w[8];
    #pragma unroll
    for (int i = 0; i < 8; i++)
        w[i] = *(const float4*)&w_ih0[grow * ISZ + i * 4];
    const int g = grow >> 9, ug = grow & 511;
    const int blk = ug >> 2, u = ug & 3;
    float* outp = &g_gx0[((size_t)t * NBLK + blk) * 256 + (g * 4 + u) * 16];
    #pragma unroll 4
    for (int b = 0; b < BT; b++) {
        float s = 0.0f;
        #pragma unroll
        for (int i = 0; i < 8; i++) {
            s += w[i].x * sx[b][i*4+0] + w[i].y * sx[b][i*4+1]
               + w[i].z * sx[b][i*4+2] + w[i].w * sx[b][i*4+3];
        }
        outp[b] = s;
    }
}

// ---- main persistent kernel (plain launch, no clusters) ---------------------
__global__ void __launch_bounds__(NTH, 1) lstm_kernel(
    const float* __restrict__ w_hh0,
    const float* __restrict__ b_ih0, const float* __restrict__ b_hh0,
    const float* __restrict__ w_ih1, const float* __restrict__ w_hh1,
    const float* __restrict__ b_ih1, const float* __restrict__ b_hh1,
    float* __restrict__ out)
{
    extern __shared__ unsigned smu[];
    float* red  = reinterpret_cast<float*>(&smu[ORED]);
    float* bias = reinterpret_cast<float*>(&smu[OBIAS]);
    const int tid = threadIdx.x;
    const int bid = blockIdx.x;
    const int j0  = bid * 4;
    const unsigned sbase = (unsigned)__cvta_generic_to_shared(smu);

    // ---- one-time: split-bf16 weights into smem, XOR-swizzled ----
    for (int i = tid; i < 16 * 256; i += NTH) {
        int r = i >> 8, w = i & 255;
        int grow = (r >> 2) * HID + j0 + (r & 3);
        float f0 = w_hh0[grow * HID + 2 * w];
        float f1 = w_hh0[grow * HID + 2 * w + 1];
        unsigned hi, lo; split2(f0, f1, hi, lo);
        int ws = w ^ ((r & 7) << 2);
        smu[OA0 + r * 256 + ws]        = hi;
        smu[OA0 + 4096 + r * 256 + ws] = lo;
    }
    for (int i = tid; i < 16 * 512; i += NTH) {
        int r = i >> 9, w = i & 511;
        int grow = (r >> 2) * HID + j0 + (r & 3);
        int c0 = 2 * w, c1 = c0 + 1;
        float f0 = (c0 < 512) ? w_ih1[grow*HID + c0] : w_hh1[grow*HID + (c0 - 512)];
        float f1 = (c1 < 512) ? w_ih1[grow*HID + c1] : w_hh1[grow*HID + (c1 - 512)];
        unsigned hi, lo; split2(f0, f1, hi, lo);
        int ws = w ^ ((r & 7) << 2);
        smu[OA1 + r * 512 + ws]        = hi;
        smu[OA1 + 8192 + r * 512 + ws] = lo;
    }
    if (tid < 32) {
        int l = tid >> 4, r = tid & 15;
        int grow = (r >> 2) * HID + j0 + (r & 3);
        bias[tid] = l ? (b_ih1[grow] + b_hh1[grow]) : (b_ih0[grow] + b_hh0[grow]);
    }
    __syncthreads();

    // ---- roles ----
    const int wid = tid >> 5, lane = tid & 31;
    const int mm = lane >> 3, rr = lane & 7;
    const int ar = rr + ((mm & 1) << 3);          // A ldmatrix row
    const unsigned aoff = (unsigned)((mm >> 1) << 2);
    const int bb = ((mm >> 1) << 3) + rr;         // B ldmatrix row (batch)
    const unsigned boff = (unsigned)((mm & 1) << 2);
    const unsigned xm = (unsigned)(rr << 2);      // swizzle xor
    const int layerA = tid >> 6, uA = (tid >> 4) & 3, bA = tid & 15;
    float c_reg = 0.0f, h_last = 0.0f;

    for (int n = 0; n <= TT; n++) {
        const int wr = n & 1, rd = wr ^ 1;

        // ---- prefetch gx0 (L0 act threads) ----
        float gx[4] = {0, 0, 0, 0};
        if (tid < 64 && n < TT) {
            const float* gp = &g_gx0[((size_t)n * NBLK + bid) * 256 + uA * 16 + bA];
            #pragma unroll
            for (int g = 0; g < 4; g++) gx[g] = __ldg(gp + g * 64);
        }

        // ---- stage packed h (raw linear copy; layout already swizzled) ----
        {
            const uint4* src = (const uint4*)&g_hp[rd][0];
            #pragma unroll
            for (int it = 0; it < 8; it++) {
                int i = tid + it * NTH;            // 0..4095
                *(uint4*)&smu[OB + i * 4] = __ldcg(&src[i]);
            }
        }
        __syncthreads();

        // ---- tensor-core GEMMs (split-bf16, A+B via ldmatrix) ----
        if (wid < 8) {
            if (n < TT) {   // layer 0: K=512, K-split 8, 4 k-tiles each
                float acc0[4] = {0,0,0,0}, acc1[4] = {0,0,0,0};
                const unsigned w0 = (unsigned)(wid * 32);
                #pragma unroll
                for (int i = 0; i < 4; i++) {
                    const unsigned w = w0 + i * 8;
                    unsigned aw = sbase + (OA0 + ar * 256 + ((w + aoff) ^ xm)) * 4u;
                    unsigned bw = sbase + (OB  + bb * 256 + ((w + boff) ^ xm)) * 4u;
                    unsigned ah[4], al[4], b0,b1,b2,b3, l0,l1,l2,l3;
                    ldsm4(ah[0], ah[1], ah[2], ah[3], aw);
                    ldsm4(al[0], al[1], al[2], al[3], aw + 4096 * 4u);
                    ldsm4(b0, b1, b2, b3, bw);
                    ldsm4(l0, l1, l2, l3, bw + 8192 * 4u);
                    unsigned bh0[2] = {b0, b1}, bh1[2] = {b2, b3};
                    unsigned bl0[2] = {l0, l1}, bl1[2] = {l2, l3};
                    mma_bf16(acc0, ah, bh0);
                    mma_bf16(acc0, ah, bl0);
                    mma_bf16(acc0, al, bh0);
                    mma_bf16(acc1, ah, bh1);
                    mma_bf16(acc1, ah, bl1);
                    mma_bf16(acc1, al, bh1);
                }
                const int base = wid * 256, row = lane >> 2, col = (lane & 3) * 2;
                *(float2*)&red[base +  row      * 16 + col    ] = make_float2(acc0[0], acc0[1]);
                *(float2*)&red[base + (row + 8) * 16 + col    ] = make_float2(acc0[2], acc0[3]);
                *(float2*)&red[base +  row      * 16 + col + 8] = make_float2(acc1[0], acc1[1]);
                *(float2*)&red[base + (row + 8) * 16 + col + 8] = make_float2(acc1[2], acc1[3]);
            }
        } else {
            if (n >= 1) {   // layer 1: K=1024, K-split 8, 8 k-tiles each
                float acc0[4] = {0,0,0,0}, acc1[4] = {0,0,0,0};
                const unsigned wA0 = (unsigned)((wid - 8) * 64);
                const unsigned Lb  = (wid >= 12) ? 4096u : 0u;
                const unsigned wB0 = (wid >= 12) ? wA0 - 256u : wA0;
                #pragma unroll
                for (int i = 0; i < 8; i++) {
                    const unsigned wA = wA0 + i * 8, wB = wB0 + i * 8;
                    unsigned aw = sbase + (OA1 + ar * 512 + ((wA + aoff) ^ xm)) * 4u;
                    unsigned bw = sbase + (OB + Lb + bb * 256 + ((wB + boff) ^ xm)) * 4u;
                    unsigned ah[4], al[4], b0,b1,b2,b3, l0,l1,l2,l3;
                    ldsm4(ah[0], ah[1], ah[2], ah[3], aw);
                    ldsm4(al[0], al[1], al[2], al[3], aw + 8192 * 4u);
                    ldsm4(b0, b1, b2, b3, bw);
                    ldsm4(l0, l1, l2, l3, bw + 8192 * 4u);
                    unsigned bh0[2] = {b0, b1}, bh1[2] = {b2, b3};
                    unsigned bl0[2] = {l0, l1}, bl1[2] = {l2, l3};
                    mma_bf16(acc0, ah, bh0);
                    mma_bf16(acc0, ah, bl0);
                    mma_bf16(acc0, al, bh0);
                    mma_bf16(acc1, ah, bh1);
                    mma_bf16(acc1, ah, bl1);
                    mma_bf16(acc1, al, bh1);
                }
                const int base = wid * 256, row = lane >> 2, col = (lane & 3) * 2;
                *(float2*)&red[base +  row      * 16 + col    ] = make_float2(acc0[0], acc0[1]);
                *(float2*)&red[base + (row + 8) * 16 + col    ] = make_float2(acc0[2], acc0[3]);
                *(float2*)&red[base +  row      * 16 + col + 8] = make_float2(acc1[0], acc1[1]);
                *(float2*)&red[base + (row + 8) * 16 + col + 8] = make_float2(acc1[2], acc1[3]);
            }
        }
        __syncthreads();

        // ---- merged reduce + activations + state update + publish ----
        if (tid < 128) {
            const bool active = layerA ? (n >= 1) : (n < TT);
            if (active) {
                float g4[4];
                const int rb = layerA * 2048;
                #pragma unroll
                for (int g = 0; g < 4; g++) {
                    const int row = g * 4 + uA;
                    const float* rp = &red[rb + row * 16 + bA];
                    float s = rp[0] + rp[256] + rp[512] + rp[768]
                            + rp[1024] + rp[1280] + rp[1536] + rp[1792];
                    g4[g] = s + bias[layerA * 16 + row] + gx[g];
                }
                float iv = sigf(g4[0]), fv = sigf(g4[1]);
                float gg = tanh_fast(g4[2]), ov = sigf(g4[3]);
                c_reg = fv * c_reg + iv * gg;
                h_last = ov * tanh_fast(c_reg);

                float hp = __shfl_xor_sync(0xffffffffu, h_last, 16);
                if ((tid & 16) == 0) {
                    unsigned whi, wlo; split2(h_last, hp, whi, wlo);
                    const int w  = bid * 2 + (uA >> 1);
                    const int ws = w ^ ((bA & 7) << 2);
                    g_hp[wr][layerA * 4096 + bA * 256 + ws]        = whi;
                    g_hp[wr][8192 + layerA * 4096 + bA * 256 + ws] = wlo;
                }
                if (layerA == 1)
                    g_h2[((size_t)(n - 1) * BT + bA) * HID + j0 + uA] = h_last;
            }
            asm volatile("fence.acq_rel.gpu;" ::: "memory");  // release publishes
        }
        grid_barrier((unsigned)(n + 1));
    }

    // ---- final h_n, c_n ----
    if (tid < 128) {
        const int j = j0 + uA;
        out[YSZ + (layerA * BT + bA) * HID + j] = h_last;
        out[YSZ + 2*BT*HID + (layerA * BT + bA) * HID + j] = c_reg;
    }
}

// ---- y projection -----------------------------------------------------------
__global__ void __launch_bounds__(256) y_proj_kernel(
    const float* __restrict__ w_out, const float* __restrict__ b_out,
    float* __restrict__ out)
{
    extern __shared__ float sm[];
    float* sWo = sm;
    float* sH  = sm + 32 * PWO;
    const int t = blockIdx.x;
    const int tid = threadIdx.x;

    for (int i = tid; i < 32 * 128; i += 256) {
        int o = i >> 7, k = (i & 127) << 2;
        *(float4*)&sWo[o * PWO + k] = *(const float4*)&w_out[o * HID + k];
    }
    for (int i = tid; i < 16 * 128; i += 256) {
        int b = i >> 7, k = (i & 127) << 2;
        *(float4*)&sH[b * HID + k] = *(const float4*)&g_h2[((size_t)t * BT + b) * HID + k];
    }
    __syncthreads();

    const int b = tid >> 4, oc = tid & 15;
    float a0 = 0.0f, a1 = 0.0f;
    #pragma unroll 4
    for (int k = 0; k < HID; k += 4) {
        float4 hk = *(const float4*)&sH[b * HID + k];
        float4 w0 = *(const float4*)&sWo[oc * PWO + k];
        float4 w1 = *(const float4*)&sWo[(oc + 16) * PWO + k];
        a0 += hk.x*w0.x + hk.y*w0.y + hk.z*w0.z + hk.w*w0.w;
        a1 += hk.x*w1.x + hk.y*w1.y + hk.z*w1.z + hk.w*w1.w;
    }
    out[((size_t)b * TT + t) * ISZ + oc]      = a0 + b_out[oc];
    out[((size_t)b * TT + t) * ISZ + oc + 16] = a1 + b_out[oc + 16];
}

// ----------------------------------------------------------------------------
extern "C" void kernel_launch(void* const* d_in, const int* in_sizes, int n_in,
                              void* d_out, int out_size)
{
    const float* x     = (const float*)d_in[0];
    const float* w_ih0 = (const float*)d_in[1];
    const float* w_hh0 = (const float*)d_in[2];
    const float* b_ih0 = (const float*)d_in[3];
    const float* b_hh0 = (const float*)d_in[4];
    const float* w_ih1 = (const float*)d_in[5];
    const float* w_hh1 = (const float*)d_in[6];
    const float* b_ih1 = (const float*)d_in[7];
    const float* b_hh1 = (const float*)d_in[8];
    const float* w_out = (const float*)d_in[9];
    const float* b_out = (const float*)d_in[10];
    float* out = (float*)d_out;

    cudaFuncSetAttribute(lstm_kernel, cudaFuncAttributeMaxDynamicSharedMemorySize, SMEM_MAIN);
    cudaFuncSetAttribute(y_proj_kernel, cudaFuncAttributeMaxDynamicSharedMemorySize, SMEM_Y);

    init_zero_kernel<<<128, 256>>>();
    {
        dim3 g(TT, 8, 1);
        gx0_kernel<<<g, 256>>>(x, w_ih0);
    }
    lstm_kernel<<<NBLK, NTH, SMEM_MAIN>>>(w_hh0, b_ih0, b_hh0,
                                          w_ih1, w_hh1, b_ih1, b_hh1, out);
    y_proj_kernel<<<TT, 256, SMEM_Y>>>(w_out, b_out, out);
}

// round 13
// speedup vs baseline: 1.0674x; 1.0088x over previous
#include <cuda_runtime.h>
#include <cuda_bf16.h>

#define HID 512
#define BT  16
#define TT  2048
#define ISZ 32
#define NBLK 128
#define NTH  512
#define YSZ (BT*TT*ISZ)

// ---- shared memory word (u32) layout ---------------------------------------
#define OA0   0                 // L0 A: hi 16x256 | lo 16x256 (w_hh0), swizzled
#define OA1   8192              // L1 A: hi 16x512 | lo 16x512 (w_ih1|w_hh1)
#define OB    24576             // B: hi [L(2)][b(16)][256] | lo same (raw copy of g_hp)
#define ORED  40960             // 16 warps x 256 floats
#define OBIAS 45056             // 32 floats
#define OWOUT 45088             // w_out row oc: 512 floats
#define SMEM_MAIN ((OWOUT + 512) * 4)

// ---- device scratch ---------------------------------------------------------
__device__ __align__(16) unsigned g_hp[2][16384];   // packed split-bf16 h (64KB/buf)
__device__ float g_gx0[(size_t)TT*NBLK*256];        // precomputed x@w_ih0^T
__device__ unsigned g_bar_count, g_bar_gen;

// ---- helpers ----------------------------------------------------------------
__device__ __forceinline__ void split2(float f0, float f1, unsigned &hi, unsigned &lo) {
    unsigned h;
    asm("cvt.rn.bf16x2.f32 %0, %1, %2;" : "=r"(h) : "f"(f1), "f"(f0));
    float r0 = f0 - __uint_as_float(h << 16);
    float r1 = f1 - __uint_as_float(h & 0xFFFF0000u);
    unsigned l;
    asm("cvt.rn.bf16x2.f32 %0, %1, %2;" : "=r"(l) : "f"(r1), "f"(r0));
    hi = h; lo = l;
}

__device__ __forceinline__ void mma_bf16(float* c, const unsigned* a, const unsigned* b) {
    asm volatile(
        "mma.sync.aligned.m16n8k16.row.col.f32.bf16.bf16.f32 "
        "{%0,%1,%2,%3}, {%4,%5,%6,%7}, {%8,%9}, {%0,%1,%2,%3};"
        : "+f"(c[0]), "+f"(c[1]), "+f"(c[2]), "+f"(c[3])
        : "r"(a[0]), "r"(a[1]), "r"(a[2]), "r"(a[3]), "r"(b[0]), "r"(b[1]));
}

__device__ __forceinline__ void ldsm4(unsigned &r0, unsigned &r1, unsigned &r2, unsigned &r3,
                                      unsigned addr) {
    asm volatile("ldmatrix.sync.aligned.m8n8.x4.shared.b16 {%0,%1,%2,%3}, [%4];"
                 : "=r"(r0), "=r"(r1), "=r"(r2), "=r"(r3) : "r"(addr));
}

__device__ __forceinline__ float sigf(float v) {
    return __fdividef(1.0f, 1.0f + __expf(-v));
}
__device__ __forceinline__ float tanh_fast(float v) {
    return __fdividef(2.0f, 1.0f + __expf(-2.0f * v)) - 1.0f;
}

// Proven barrier (R12): monotonic ticket count, local target, store release.
__device__ __forceinline__ void grid_barrier(unsigned target) {
    __syncthreads();
    if (threadIdx.x == 0) {
        unsigned ticket = atomicAdd(&g_bar_count, 1u);
        if (ticket == target * NBLK - 1u) {
            __threadfence();
            *(volatile unsigned*)&g_bar_gen = target;
        } else {
            volatile unsigned* genp = &g_bar_gen;
            while (*genp < target) { }
        }
        asm volatile("fence.acq_rel.gpu;" ::: "memory");  // acquire for h reads
    }
    __syncthreads();
}

// ---- init -------------------------------------------------------------------
__global__ void init_zero_kernel() {
    int i = blockIdx.x * blockDim.x + threadIdx.x;
    if (i < 2 * 16384) (&g_hp[0][0])[i] = 0u;
    if (i == 0) { g_bar_count = 0u; g_bar_gen = 0u; }
}

// gx0[t][blk][g*4+u][b] = dot(x[b,t,:], w_ih0[g*512+blk*4+u, :])
__global__ void gx0_kernel(const float* __restrict__ x, const float* __restrict__ w_ih0) {
    __shared__ float sx[BT][ISZ];
    const int t = blockIdx.x;
    const int tid = threadIdx.x;
    for (int i = tid; i < BT * ISZ; i += 256) {
        int b = i >> 5, k = i & 31;
        sx[b][k] = x[((size_t)b * TT + t) * ISZ + k];
    }
    __syncthreads();
    const int grow = blockIdx.y * 256 + tid;   // 0..2047
    float4 w[8];
    #pragma unroll
    for (int i = 0; i < 8; i++)
        w[i] = *(const float4*)&w_ih0[grow * ISZ + i * 4];
    const int g = grow >> 9, ug = grow & 511;
    const int blk = ug >> 2, u = ug & 3;
    float* outp = &g_gx0[((size_t)t * NBLK + blk) * 256 + (g * 4 + u) * 16];
    #pragma unroll 4
    for (int b = 0; b < BT; b++) {
        float s = 0.0f;
        #pragma unroll
        for (int i = 0; i < 8; i++) {
            s += w[i].x * sx[b][i*4+0] + w[i].y * sx[b][i*4+1]
               + w[i].z * sx[b][i*4+2] + w[i].w * sx[b][i*4+3];
        }
        outp[b] = s;
    }
}

// ---- main persistent kernel (plain launch, no clusters) ---------------------
__global__ void __launch_bounds__(NTH, 1) lstm_kernel(
    const float* __restrict__ w_hh0,
    const float* __restrict__ b_ih0, const float* __restrict__ b_hh0,
    const float* __restrict__ w_ih1, const float* __restrict__ w_hh1,
    const float* __restrict__ b_ih1, const float* __restrict__ b_hh1,
    const float* __restrict__ w_out, const float* __restrict__ b_out,
    float* __restrict__ out)
{
    extern __shared__ unsigned smu[];
    float* red  = reinterpret_cast<float*>(&smu[ORED]);
    float* bias = reinterpret_cast<float*>(&smu[OBIAS]);
    float* sWo  = reinterpret_cast<float*>(&smu[OWOUT]);
    const int tid = threadIdx.x;
    const int bid = blockIdx.x;
    const int j0  = bid * 4;
    const unsigned sbase = (unsigned)__cvta_generic_to_shared(smu);

    // y role: block owns output channel oc for 4 batches
    const int oc = bid & 31;
    const float bo = __ldg(&b_out[oc]);

    // ---- one-time: split-bf16 weights into smem, XOR-swizzled ----
    for (int i = tid; i < 16 * 256; i += NTH) {
        int r = i >> 8, w = i & 255;
        int grow = (r >> 2) * HID + j0 + (r & 3);
        float f0 = w_hh0[grow * HID + 2 * w];
        float f1 = w_hh0[grow * HID + 2 * w + 1];
        unsigned hi, lo; split2(f0, f1, hi, lo);
        int ws = w ^ ((r & 7) << 2);
        smu[OA0 + r * 256 + ws]        = hi;
        smu[OA0 + 4096 + r * 256 + ws] = lo;
    }
    for (int i = tid; i < 16 * 512; i += NTH) {
        int r = i >> 9, w = i & 511;
        int grow = (r >> 2) * HID + j0 + (r & 3);
        int c0 = 2 * w, c1 = c0 + 1;
        float f0 = (c0 < 512) ? w_ih1[grow*HID + c0] : w_hh1[grow*HID + (c0 - 512)];
        float f1 = (c1 < 512) ? w_ih1[grow*HID + c1] : w_hh1[grow*HID + (c1 - 512)];
        unsigned hi, lo; split2(f0, f1, hi, lo);
        int ws = w ^ ((r & 7) << 2);
        smu[OA1 + r * 512 + ws]        = hi;
        smu[OA1 + 8192 + r * 512 + ws] = lo;
    }
    if (tid < 32) {
        int l = tid >> 4, r = tid & 15;
        int grow = (r >> 2) * HID + j0 + (r & 3);
        bias[tid] = l ? (b_ih1[grow] + b_hh1[grow]) : (b_ih0[grow] + b_hh0[grow]);
    }
    for (int i = tid; i < 512; i += NTH)
        sWo[i] = w_out[oc * HID + i];
    __syncthreads();

    // ---- roles ----
    const int wid = tid >> 5, lane = tid & 31;
    const int mm = lane >> 3, rr = lane & 7;
    const int ar = rr + ((mm & 1) << 3);          // A ldmatrix row
    const unsigned aoff = (unsigned)((mm >> 1) << 2);
    const int bb = ((mm >> 1) << 3) + rr;         // B ldmatrix row (batch)
    const unsigned boff = (unsigned)((mm & 1) << 2);
    const unsigned xm = (unsigned)(rr << 2);      // swizzle xor
    const int layerA = tid >> 6, uA = (tid >> 4) & 3, bA = tid & 15;
    // y role (warps 4-7): batch for this warp
    const int yb = (bid >> 5) * 4 + (wid - 4);
    const unsigned xb = (unsigned)((yb & 7) << 2);
    float c_reg = 0.0f, h_last = 0.0f;

    for (int n = 0; n <= TT; n++) {
        const int wr = n & 1, rd = wr ^ 1;

        // ---- prefetch gx0 (L0 act threads) ----
        float gx[4] = {0, 0, 0, 0};
        if (tid < 64 && n < TT) {
            const float* gp = &g_gx0[((size_t)n * NBLK + bid) * 256 + uA * 16 + bA];
            #pragma unroll
            for (int g = 0; g < 4; g++) gx[g] = __ldg(gp + g * 64);
        }

        // ---- stage packed h (raw linear copy; layout already swizzled) ----
        {
            const uint4* src = (const uint4*)&g_hp[rd][0];
            #pragma unroll
            for (int it = 0; it < 8; it++) {
                int i = tid + it * NTH;            // 0..4095
                *(uint4*)&smu[OB + i * 4] = __ldcg(&src[i]);
            }
        }
        __syncthreads();

        // ---- tensor-core GEMMs (split-bf16, A+B via ldmatrix) ----
        if (wid < 8) {
            if (n < TT) {   // layer 0: K=512, K-split 8, 4 k-tiles each
                float acc0[4] = {0,0,0,0}, acc1[4] = {0,0,0,0};
                const unsigned w0 = (unsigned)(wid * 32);
                #pragma unroll
                for (int i = 0; i < 4; i++) {
                    const unsigned w = w0 + i * 8;
                    unsigned aw = sbase + (OA0 + ar * 256 + ((w + aoff) ^ xm)) * 4u;
                    unsigned bw = sbase + (OB  + bb * 256 + ((w + boff) ^ xm)) * 4u;
                    unsigned ah[4], al[4], b0,b1,b2,b3, l0,l1,l2,l3;
                    ldsm4(ah[0], ah[1], ah[2], ah[3], aw);
                    ldsm4(al[0], al[1], al[2], al[3], aw + 4096 * 4u);
                    ldsm4(b0, b1, b2, b3, bw);
                    ldsm4(l0, l1, l2, l3, bw + 8192 * 4u);
                    unsigned bh0[2] = {b0, b1}, bh1[2] = {b2, b3};
                    unsigned bl0[2] = {l0, l1}, bl1[2] = {l2, l3};
                    mma_bf16(acc0, ah, bh0);
                    mma_bf16(acc0, ah, bl0);
                    mma_bf16(acc0, al, bh0);
                    mma_bf16(acc1, ah, bh1);
                    mma_bf16(acc1, ah, bl1);
                    mma_bf16(acc1, al, bh1);
                }
                const int base = wid * 256, row = lane >> 2, col = (lane & 3) * 2;
                *(float2*)&red[base +  row      * 16 + col    ] = make_float2(acc0[0], acc0[1]);
                *(float2*)&red[base + (row + 8) * 16 + col    ] = make_float2(acc0[2], acc0[3]);
                *(float2*)&red[base +  row      * 16 + col + 8] = make_float2(acc1[0], acc1[1]);
                *(float2*)&red[base + (row + 8) * 16 + col + 8] = make_float2(acc1[2], acc1[3]);
            }
        } else {
            if (n >= 1) {   // layer 1: K=1024, K-split 8, 8 k-tiles each
                float acc0[4] = {0,0,0,0}, acc1[4] = {0,0,0,0};
                const unsigned wA0 = (unsigned)((wid - 8) * 64);
                const unsigned Lb  = (wid >= 12) ? 4096u : 0u;
                const unsigned wB0 = (wid >= 12) ? wA0 - 256u : wA0;
                #pragma unroll
                for (int i = 0; i < 8; i++) {
                    const unsigned wA = wA0 + i * 8, wB = wB0 + i * 8;
                    unsigned aw = sbase + (OA1 + ar * 512 + ((wA + aoff) ^ xm)) * 4u;
                    unsigned bw = sbase + (OB + Lb + bb * 256 + ((wB + boff) ^ xm)) * 4u;
                    unsigned ah[4], al[4], b0,b1,b2,b3, l0,l1,l2,l3;
                    ldsm4(ah[0], ah[1], ah[2], ah[3], aw);
                    ldsm4(al[0], al[1], al[2], al[3], aw + 8192 * 4u);
                    ldsm4(b0, b1, b2, b3, bw);
                    ldsm4(l0, l1, l2, l3, bw + 8192 * 4u);
                    unsigned bh0[2] = {b0, b1}, bh1[2] = {b2, b3};
                    unsigned bl0[2] = {l0, l1}, bl1[2] = {l2, l3};
                    mma_bf16(acc0, ah, bh0);
                    mma_bf16(acc0, ah, bl0);
                    mma_bf16(acc0, al, bh0);
                    mma_bf16(acc1, ah, bh1);
                    mma_bf16(acc1, ah, bl1);
                    mma_bf16(acc1, al, bh1);
                }
                const int base = wid * 256, row = lane >> 2, col = (lane & 3) * 2;
                *(float2*)&red[base +  row      * 16 + col    ] = make_float2(acc0[0], acc0[1]);
                *(float2*)&red[base + (row + 8) * 16 + col    ] = make_float2(acc0[2], acc0[3]);
                *(float2*)&red[base +  row      * 16 + col + 8] = make_float2(acc1[0], acc1[1]);
                *(float2*)&red[base + (row + 8) * 16 + col + 8] = make_float2(acc1[2], acc1[3]);
            }
        }
        __syncthreads();

        // ---- act warps (0-3): reduce + activations + state update + publish
        //      y warps (4-7): compute y(n-2) from staged hB (runs concurrently)
        if (tid < 128) {
            const bool active = layerA ? (n >= 1) : (n < TT);
            if (active) {
                float g4[4];
                const int rb = layerA * 2048;
                #pragma unroll
                for (int g = 0; g < 4; g++) {
                    const int row = g * 4 + uA;
                    const float* rp = &red[rb + row * 16 + bA];
                    float s = rp[0] + rp[256] + rp[512] + rp[768]
                            + rp[1024] + rp[1280] + rp[1536] + rp[1792];
                    g4[g] = s + bias[layerA * 16 + row] + gx[g];
                }
                float iv = sigf(g4[0]), fv = sigf(g4[1]);
                float gg = tanh_fast(g4[2]), ov = sigf(g4[3]);
                c_reg = fv * c_reg + iv * gg;
                h_last = ov * tanh_fast(c_reg);

                float hp = __shfl_xor_sync(0xffffffffu, h_last, 16);
                if ((tid & 16) == 0) {
                    unsigned whi, wlo; split2(h_last, hp, whi, wlo);
                    const int w  = bid * 2 + (uA >> 1);
                    const int ws = w ^ ((bA & 7) << 2);
                    g_hp[wr][layerA * 4096 + bA * 256 + ws]        = whi;
                    g_hp[wr][8192 + layerA * 4096 + bA * 256 + ws] = wlo;
                }
            }
            asm volatile("fence.acq_rel.gpu;" ::: "memory");  // release publishes
        } else if (wid < 8 && n >= 2) {
            // y[yb][n-2][oc] from staged hB = h1(n-2): h = hi + lo (exact)
            const int t = n - 2;
            float acc = 0.0f;
            #pragma unroll
            for (int i = 0; i < 8; i++) {
                const int w = lane + 32 * i;
                const unsigned idx = (unsigned)(yb * 256) + ((unsigned)w ^ xb);
                unsigned hiw = smu[OB + 4096 + idx];
                unsigned low = smu[OB + 12288 + idx];
                float he = __uint_as_float(hiw << 16) + __uint_as_float(low << 16);
                float ho = __uint_as_float(hiw & 0xFFFF0000u)
                         + __uint_as_float(low & 0xFFFF0000u);
                float2 wv = *(const float2*)&sWo[2 * w];
                acc = fmaf(he, wv.x, acc);
                acc = fmaf(ho, wv.y, acc);
            }
            #pragma unroll
            for (int s = 16; s; s >>= 1)
                acc += __shfl_xor_sync(0xffffffffu, acc, s);
            if (lane == 0)
                out[((size_t)yb * TT + t) * ISZ + oc] = acc + bo;
        }
        grid_barrier((unsigned)(n + 1));
    }

    // ---- epilogue: y(TT-1) from g_hp[0] (published at final iteration) ----
    if (wid >= 4 && wid < 8) {
        float acc = 0.0f;
        #pragma unroll
        for (int i = 0; i < 8; i++) {
            const int w = lane + 32 * i;
            const unsigned idx = (unsigned)(yb * 256) + ((unsigned)w ^ xb);
            unsigned hiw = __ldcg(&g_hp[0][4096 + idx]);
            unsigned low = __ldcg(&g_hp[0][12288 + idx]);
            float he = __uint_as_float(hiw << 16) + __uint_as_float(low << 16);
            float ho = __uint_as_float(hiw & 0xFFFF0000u)
                     + __uint_as_float(low & 0xFFFF0000u);
            float2 wv = *(const float2*)&sWo[2 * w];
            acc = fmaf(he, wv.x, acc);
            acc = fmaf(ho, wv.y, acc);
        }
        #pragma unroll
        for (int s = 16; s; s >>= 1)
            acc += __shfl_xor_sync(0xffffffffu, acc, s);
        if (lane == 0)
            out[((size_t)yb * TT + (TT - 1)) * ISZ + oc] = acc + bo;
    }

    // ---- final h_n, c_n ----
    if (tid < 128) {
        const int j = j0 + uA;
        out[YSZ + (layerA * BT + bA) * HID + j] = h_last;
        out[YSZ + 2*BT*HID + (layerA * BT + bA) * HID + j] = c_reg;
    }
}

// ----------------------------------------------------------------------------
extern "C" void kernel_launch(void* const* d_in, const int* in_sizes, int n_in,
                              void* d_out, int out_size)
{
    const float* x     = (const float*)d_in[0];
    const float* w_ih0 = (const float*)d_in[1];
    const float* w_hh0 = (const float*)d_in[2];
    const float* b_ih0 = (const float*)d_in[3];
    const float* b_hh0 = (const float*)d_in[4];
    const float* w_ih1 = (const float*)d_in[5];
    const float* w_hh1 = (const float*)d_in[6];
    const float* b_ih1 = (const float*)d_in[7];
    const float* b_hh1 = (const float*)d_in[8];
    const float* w_out = (const float*)d_in[9];
    const float* b_out = (const float*)d_in[10];
    float* out = (float*)d_out;

    cudaFuncSetAttribute(lstm_kernel, cudaFuncAttributeMaxDynamicSharedMemorySize, SMEM_MAIN);

    init_zero_kernel<<<128, 256>>>();
    {
        dim3 g(TT, 8, 1);
        gx0_kernel<<<g, 256>>>(x, w_ih0);
    }
    lstm_kernel<<<NBLK, NTH, SMEM_MAIN>>>(w_hh0, b_ih0, b_hh0,
                                          w_ih1, w_hh1, b_ih1, b_hh1,
                                          w_out, b_out, out);
}